// round 2
// baseline (speedup 1.0000x reference)
#include <cuda_runtime.h>
#include <math.h>

#define Ntot 48000
#define Hh   128
#define NPRc 3000
#define EPRc 6000
#define NC   512      // C columns: [0,384) iou_x, [384,512) wf_x

// static scratch (no allocations allowed)
__device__ float g_C[(size_t)Ntot * NC];   // 98.3 MB
__device__ float g_c[(size_t)Ntot * Hh];   // 24.6 MB

union F2U { float2 f; unsigned long long u; };

__device__ __forceinline__ float2 ffma2(float2 a, float2 b, float2 c) {
    F2U A, B, Cc, D;
    A.f = a; B.f = b; Cc.f = c;
    asm("fma.rn.f32x2 %0, %1, %2, %3;" : "=l"(D.u) : "l"(A.u), "l"(B.u), "l"(Cc.u));
    return D.f;
}

__device__ __forceinline__ float sigf(float x) { return 1.0f / (1.0f + expf(-x)); }

// ---------------------------------------------------------------------------
// Precompute C[n][0:384] = x[n] @ W_iou^T, C[n][384:512] = x[n] @ W_f^T
// grid 148, 256 thr. Thread owns 2 output cols (t, t+256), rows tiled by 16.
// ---------------------------------------------------------------------------
#define PRE_RPB 325
#define PRE_SUB 16

__global__ __launch_bounds__(256) void k_pre(const float* __restrict__ x,
                                             const float* __restrict__ W_iou,
                                             const float* __restrict__ W_f) {
    __shared__ float xs[PRE_SUB][128];
    int t = threadIdx.x;
    const float* r0p = W_iou + t * 128;                                   // col t   (<384)
    const float* r1p = (t < 128) ? (W_iou + (256 + t) * 128)              // col 256+t
                                 : (W_f + (t - 128) * 128);               // wf col
    int rowEnd = min((int)(blockIdx.x + 1) * PRE_RPB, Ntot);
    for (int rs = blockIdx.x * PRE_RPB; rs < rowEnd; rs += PRE_SUB) {
        int nr = min(PRE_SUB, rowEnd - rs);
        __syncthreads();
        for (int idx = t; idx < nr * 32; idx += 256) {
            int rr = idx >> 5, q = idx & 31;
            ((float4*)xs[rr])[q] = ((const float4*)(x + (size_t)(rs + rr) * 128))[q];
        }
        __syncthreads();
        float2 a0[PRE_SUB], a1[PRE_SUB];
#pragma unroll
        for (int r = 0; r < PRE_SUB; r++) { a0[r] = make_float2(0.f, 0.f); a1[r] = make_float2(0.f, 0.f); }
#pragma unroll 1
        for (int k0 = 0; k0 < 128; k0 += 16) {
            float2 w0[8], w1[8];
#pragma unroll
            for (int q = 0; q < 4; q++) {
                float4 v0 = *(const float4*)(r0p + k0 + 4 * q);
                float4 v1 = *(const float4*)(r1p + k0 + 4 * q);
                w0[2*q] = make_float2(v0.x, v0.y); w0[2*q+1] = make_float2(v0.z, v0.w);
                w1[2*q] = make_float2(v1.x, v1.y); w1[2*q+1] = make_float2(v1.z, v1.w);
            }
#pragma unroll
            for (int kk = 0; kk < 8; kk++) {
#pragma unroll
                for (int r = 0; r < PRE_SUB; r++) {
                    float2 xv = *(const float2*)&xs[r][k0 + 2 * kk];
                    a0[r] = ffma2(w0[kk], xv, a0[r]);
                    a1[r] = ffma2(w1[kk], xv, a1[r]);
                }
            }
        }
        for (int r = 0; r < nr; r++) {
            g_C[(size_t)(rs + r) * NC + t]       = a0[r].x + a0[r].y;
            g_C[(size_t)(rs + r) * NC + 256 + t] = a1[r].x + a1[r].y;
        }
    }
}

// ---------------------------------------------------------------------------
// Round 0: leaves. iou_mid = 0, c = 0.
// ---------------------------------------------------------------------------
__global__ __launch_bounds__(256) void k_round0(float* __restrict__ h,
                                                const int* __restrict__ order0,
                                                const float* __restrict__ b_iou) {
    int idx = blockIdx.x * 256 + threadIdx.x;
    if (idx >= NPRc * Hh) return;
    int j = idx >> 7, m = idx & 127;
    int node = order0[j];
    const float* Cp = g_C + (size_t)node * NC;
    float gi = Cp[m]       + b_iou[m];
    float go = Cp[128 + m] + b_iou[128 + m];
    float gu = Cp[256 + m] + b_iou[256 + m];
    float ct = sigf(gi) * tanhf(gu);
    g_c[(size_t)node * Hh + m] = ct;
    h[(size_t)node * Hh + m]   = sigf(go) * tanhf(ct);
}

// ---------------------------------------------------------------------------
// One topological round, fully fused. grid 148, 256 thr, 21 parents/block.
// Per parent: gsum = he2_a + he2_b (dense 256), iou = U_iou @ gsum (no label
// selects!); f_a = U_f @ he2_a, f_b = U_f @ he2_b (dense-256, zero half).
// Outputs per parent: 640 = 384 iou + 128 fa + 128 fb.
//   t<128 (warps 0-3): cols t (iou-i), 256+t (iou-u), fb[t]     -> 3 accs
//   t>=128 (warps 4-7): cols t (iou-o), fa[t-128]               -> 2 accs
// (3+2 split balances per-SMSP: each SMSP hosts one heavy + one light warp)
// ---------------------------------------------------------------------------
#define PPB  21
#define PSUB 8

__global__ __launch_bounds__(256) void k_round(int ri,
        float* __restrict__ h,
        const float* __restrict__ U_iou, const float* __restrict__ U_f,
        const float* __restrict__ b_iou, const float* __restrict__ b_f,
        const int* __restrict__ edges_r, const float* __restrict__ labels) {
    __shared__ float gs[PSUB * 768];    // per parent: [0,256) gsum | [256,512) he2_a | [512,768) he2_b
    __shared__ float epi[PSUB * 640];   // per parent: [0,384) iou | [384,512) z_fa | [512,640) z_fb
    __shared__ int s_child[2 * PSUB];
    __shared__ int s_lab[2 * PSUB];
    __shared__ int s_par[PSUB];

    int t = threadIdx.x;
    const int*   e_src   = edges_r + ri * 2 * EPRc;
    const int*   e_child = e_src + EPRc;
    const float* labp    = labels + ri * EPRc;

    const float *rowA0 = U_iou, *rowA1 = U_iou, *rowA2 = U_f;
    const float *rowB0 = U_iou, *rowB1 = U_f;
    if (t < 128) {
        rowA0 = U_iou + t * 256;
        rowA1 = U_iou + (256 + t) * 256;
        rowA2 = U_f + t * 256;
    } else {
        rowB0 = U_iou + t * 256;
        rowB1 = U_f + (t - 128) * 256;
    }

    int pend = min((int)(blockIdx.x + 1) * PPB, NPRc);
    for (int ps = blockIdx.x * PPB; ps < pend; ps += PSUB) {
        int np = min(PSUB, pend - ps);
        __syncthreads();   // protect s_* / gs vs previous sub-batch readers
        if (t < 2 * np) {
            int e = 2 * ps + t;
            s_child[t] = e_child[e];
            s_lab[t]   = (labp[e] != 0.0f) ? 1 : 0;
        }
        if (t < np) s_par[t] = e_src[2 * (ps + t)];
        __syncthreads();

        // build he2_a / he2_b  (h in half 'lab', zero elsewhere)
        for (int idx = t; idx < np * 128; idx += 256) {       // 2*np edges * 64 float4
            int e = idx >> 6, q = idx & 63;
            float4 v = make_float4(0.f, 0.f, 0.f, 0.f);
            if ((q >> 5) == s_lab[e])
                v = ((const float4*)(h + (size_t)s_child[e] * Hh))[q & 31];
            int p = e >> 1, eo = e & 1;
            *((float4*)(gs + p * 768 + 256 + eo * 256) + q) = v;
        }
        __syncthreads();
        // gsum = he2_a + he2_b
        for (int idx = t; idx < np * 64; idx += 256) {
            int p = idx >> 6, q = idx & 63;
            float4 a = *((const float4*)(gs + p * 768 + 256) + q);
            float4 b = *((const float4*)(gs + p * 768 + 512) + q);
            *((float4*)(gs + p * 768) + q) = make_float4(a.x + b.x, a.y + b.y, a.z + b.z, a.w + b.w);
        }
        __syncthreads();

        if (t < 128) {
            float2 a0[PSUB], a1[PSUB], a2[PSUB];
#pragma unroll
            for (int p = 0; p < PSUB; p++) { a0[p] = make_float2(0.f,0.f); a1[p] = make_float2(0.f,0.f); a2[p] = make_float2(0.f,0.f); }
#pragma unroll 1
            for (int k0 = 0; k0 < 256; k0 += 16) {
                float2 w0[8], w1[8], w2[8];
#pragma unroll
                for (int q = 0; q < 4; q++) {
                    float4 v0 = *(const float4*)(rowA0 + k0 + 4 * q);
                    float4 v1 = *(const float4*)(rowA1 + k0 + 4 * q);
                    float4 v2 = *(const float4*)(rowA2 + k0 + 4 * q);
                    w0[2*q] = make_float2(v0.x,v0.y); w0[2*q+1] = make_float2(v0.z,v0.w);
                    w1[2*q] = make_float2(v1.x,v1.y); w1[2*q+1] = make_float2(v1.z,v1.w);
                    w2[2*q] = make_float2(v2.x,v2.y); w2[2*q+1] = make_float2(v2.z,v2.w);
                }
#pragma unroll
                for (int kk = 0; kk < 8; kk++) {
#pragma unroll
                    for (int p = 0; p < PSUB; p++) {
                        float2 g0 = *(const float2*)&gs[p * 768 + k0 + 2 * kk];        // gsum
                        float2 g2 = *(const float2*)&gs[p * 768 + 512 + k0 + 2 * kk];  // he2_b
                        a0[p] = ffma2(w0[kk], g0, a0[p]);
                        a1[p] = ffma2(w1[kk], g0, a1[p]);
                        a2[p] = ffma2(w2[kk], g2, a2[p]);
                    }
                }
            }
#pragma unroll
            for (int p = 0; p < PSUB; p++) {
                epi[p * 640 + t]       = a0[p].x + a0[p].y;   // iou col t
                epi[p * 640 + 256 + t] = a1[p].x + a1[p].y;   // iou col 256+t
                epi[p * 640 + 512 + t] = a2[p].x + a2[p].y;   // z_fb[t]
            }
        } else {
            float2 a0[PSUB], a1[PSUB];
#pragma unroll
            for (int p = 0; p < PSUB; p++) { a0[p] = make_float2(0.f,0.f); a1[p] = make_float2(0.f,0.f); }
#pragma unroll 1
            for (int k0 = 0; k0 < 256; k0 += 16) {
                float2 w0[8], w1[8];
#pragma unroll
                for (int q = 0; q < 4; q++) {
                    float4 v0 = *(const float4*)(rowB0 + k0 + 4 * q);
                    float4 v1 = *(const float4*)(rowB1 + k0 + 4 * q);
                    w0[2*q] = make_float2(v0.x,v0.y); w0[2*q+1] = make_float2(v0.z,v0.w);
                    w1[2*q] = make_float2(v1.x,v1.y); w1[2*q+1] = make_float2(v1.z,v1.w);
                }
#pragma unroll
                for (int kk = 0; kk < 8; kk++) {
#pragma unroll
                    for (int p = 0; p < PSUB; p++) {
                        float2 g0 = *(const float2*)&gs[p * 768 + k0 + 2 * kk];        // gsum
                        float2 g1 = *(const float2*)&gs[p * 768 + 256 + k0 + 2 * kk];  // he2_a
                        a0[p] = ffma2(w0[kk], g0, a0[p]);
                        a1[p] = ffma2(w1[kk], g1, a1[p]);
                    }
                }
            }
#pragma unroll
            for (int p = 0; p < PSUB; p++) {
                epi[p * 640 + t]                = a0[p].x + a0[p].y;   // iou col t
                epi[p * 640 + 384 + (t - 128)]  = a1[p].x + a1[p].y;   // z_fa[t-128]
            }
        }
        __syncthreads();

        // epilogue: f gates, c accumulation, node_update
        for (int idx = t; idx < np * Hh; idx += 256) {
            int pl = idx >> 7, m = idx & 127;
            int par = s_par[pl];
            int cA = s_child[2 * pl], cB = s_child[2 * pl + 1];
            const float* Cp = g_C + (size_t)par * NC;
            float gi = Cp[m]       + epi[pl * 640 + m]       + b_iou[m];
            float go = Cp[128 + m] + epi[pl * 640 + 128 + m] + b_iou[128 + m];
            float gu = Cp[256 + m] + epi[pl * 640 + 256 + m] + b_iou[256 + m];
            float fa = sigf(g_C[(size_t)cA * NC + 384 + m] + epi[pl * 640 + 384 + m] + b_f[m]);
            float fb = sigf(g_C[(size_t)cB * NC + 384 + m] + epi[pl * 640 + 512 + m] + b_f[m]);
            float ca = g_c[(size_t)cA * Hh + m]; ca = fminf(fmaxf(ca, -1e14f), 1e14f);
            float cb = g_c[(size_t)cB * Hh + m]; cb = fminf(fmaxf(cb, -1e14f), 1e14f);
            float ct = sigf(gi) * tanhf(gu) + fa * ca + fb * cb;
            g_c[(size_t)par * Hh + m] = ct;
            h[(size_t)par * Hh + m]   = sigf(go) * tanhf(ct);
        }
    }
}

// ---------------------------------------------------------------------------
extern "C" void kernel_launch(void* const* d_in, const int* in_sizes, int n_in,
                              void* d_out, int out_size) {
    const float* x      = (const float*)d_in[0];
    const float* labels = (const float*)d_in[1];   // [15,6000,1]
    const float* W_iou  = (const float*)d_in[2];
    const float* W_f    = (const float*)d_in[3];
    const float* b_iou  = (const float*)d_in[4];
    const float* b_f    = (const float*)d_in[5];
    const float* U_iou  = (const float*)d_in[6];
    const float* U_f    = (const float*)d_in[7];
    const int*   edges  = (const int*)d_in[8];     // [15,2,6000]
    const int*   order0 = (const int*)d_in[9];
    float* h = (float*)d_out;                      // h lives directly in d_out

    k_pre<<<148, 256>>>(x, W_iou, W_f);
    k_round0<<<(NPRc * Hh + 255) / 256, 256>>>(h, order0, b_iou);
    for (int ri = 0; ri < 15; ri++)
        k_round<<<148, 256>>>(ri, h, U_iou, U_f, b_iou, b_f, edges, labels);
}

// round 3
// speedup vs baseline: 1.0029x; 1.0029x over previous
#include <cuda_runtime.h>
#include <math.h>

#define Ntot 48000
#define Hh   128
#define NPRc 3000
#define EPRc 6000
#define NC   512      // C columns: [0,384) iou_x, [384,512) wf_x

// static scratch (no allocations allowed)
__device__ float g_C[(size_t)Ntot * NC];   // 98.3 MB
__device__ float g_c[(size_t)Ntot * Hh];   // 24.6 MB

union F2U { float2 f; unsigned long long u; };

__device__ __forceinline__ float2 ffma2(float2 a, float2 b, float2 c) {
    F2U A, B, Cc, D;
    A.f = a; B.f = b; Cc.f = c;
    asm("fma.rn.f32x2 %0, %1, %2, %3;" : "=l"(D.u) : "l"(A.u), "l"(B.u), "l"(Cc.u));
    return D.f;
}

__device__ __forceinline__ float sigf(float x) { return 1.0f / (1.0f + expf(-x)); }

// ---------------------------------------------------------------------------
// Precompute C[n][0:384] = x[n] @ W_iou^T, C[n][384:512] = x[n] @ W_f^T
// grid 148, 256 thr. Thread owns 2 output cols (t, t+256), rows tiled by 16.
// ---------------------------------------------------------------------------
#define PRE_RPB 325
#define PRE_SUB 16

__global__ __launch_bounds__(256) void k_pre(const float* __restrict__ x,
                                             const float* __restrict__ W_iou,
                                             const float* __restrict__ W_f) {
    __shared__ float xs[PRE_SUB][128];
    int t = threadIdx.x;
    const float* r0p = W_iou + t * 128;                                   // col t   (<384)
    const float* r1p = (t < 128) ? (W_iou + (256 + t) * 128)              // col 256+t
                                 : (W_f + (t - 128) * 128);               // wf col
    int rowEnd = min((int)(blockIdx.x + 1) * PRE_RPB, Ntot);
    for (int rs = blockIdx.x * PRE_RPB; rs < rowEnd; rs += PRE_SUB) {
        int nr = min(PRE_SUB, rowEnd - rs);
        __syncthreads();
        for (int idx = t; idx < nr * 32; idx += 256) {
            int rr = idx >> 5, q = idx & 31;
            ((float4*)xs[rr])[q] = ((const float4*)(x + (size_t)(rs + rr) * 128))[q];
        }
        __syncthreads();
        float2 a0[PRE_SUB], a1[PRE_SUB];
#pragma unroll
        for (int r = 0; r < PRE_SUB; r++) { a0[r] = make_float2(0.f, 0.f); a1[r] = make_float2(0.f, 0.f); }
#pragma unroll 1
        for (int k0 = 0; k0 < 128; k0 += 16) {
            float2 w0[8], w1[8];
#pragma unroll
            for (int q = 0; q < 4; q++) {
                float4 v0 = *(const float4*)(r0p + k0 + 4 * q);
                float4 v1 = *(const float4*)(r1p + k0 + 4 * q);
                w0[2*q] = make_float2(v0.x, v0.y); w0[2*q+1] = make_float2(v0.z, v0.w);
                w1[2*q] = make_float2(v1.x, v1.y); w1[2*q+1] = make_float2(v1.z, v1.w);
            }
#pragma unroll
            for (int kk = 0; kk < 8; kk++) {
#pragma unroll
                for (int r = 0; r < PRE_SUB; r++) {
                    float2 xv = *(const float2*)&xs[r][k0 + 2 * kk];
                    a0[r] = ffma2(w0[kk], xv, a0[r]);
                    a1[r] = ffma2(w1[kk], xv, a1[r]);
                }
            }
        }
        for (int r = 0; r < nr; r++) {
            g_C[(size_t)(rs + r) * NC + t]       = a0[r].x + a0[r].y;
            g_C[(size_t)(rs + r) * NC + 256 + t] = a1[r].x + a1[r].y;
        }
    }
}

// ---------------------------------------------------------------------------
// Round 0: leaves. iou_mid = 0, c = 0.
// ---------------------------------------------------------------------------
__global__ __launch_bounds__(256) void k_round0(float* __restrict__ h,
                                                const int* __restrict__ order0,
                                                const float* __restrict__ b_iou) {
    int idx = blockIdx.x * 256 + threadIdx.x;
    if (idx >= NPRc * Hh) return;
    int j = idx >> 7, m = idx & 127;
    int node = order0[j];
    const float* Cp = g_C + (size_t)node * NC;
    float gi = Cp[m]       + b_iou[m];
    float go = Cp[128 + m] + b_iou[128 + m];
    float gu = Cp[256 + m] + b_iou[256 + m];
    float ct = sigf(gi) * tanhf(gu);
    g_c[(size_t)node * Hh + m] = ct;
    h[(size_t)node * Hh + m]   = sigf(go) * tanhf(ct);
}

// ---------------------------------------------------------------------------
// One topological round, fully fused. grid 148, 256 thr, 21 parents/block.
// Per parent: gsum = he2_a + he2_b (dense 256), iou = U_iou @ gsum (no label
// selects!); f_a = U_f @ he2_a, f_b = U_f @ he2_b (dense-256, zero half).
// Outputs per parent: 640 = 384 iou + 128 fa + 128 fb.
//   t<128 (warps 0-3): cols t (iou-i), 256+t (iou-u), fb[t]     -> 3 accs
//   t>=128 (warps 4-7): cols t (iou-o), fa[t-128]               -> 2 accs
// (3+2 split balances per-SMSP: each SMSP hosts one heavy + one light warp)
// ---------------------------------------------------------------------------
#define PPB  21
#define PSUB 8

__global__ __launch_bounds__(256) void k_round(int ri,
        float* __restrict__ h,
        const float* __restrict__ U_iou, const float* __restrict__ U_f,
        const float* __restrict__ b_iou, const float* __restrict__ b_f,
        const int* __restrict__ edges_r, const float* __restrict__ labels) {
    __shared__ float gs[PSUB * 768];    // per parent: [0,256) gsum | [256,512) he2_a | [512,768) he2_b
    __shared__ float epi[PSUB * 640];   // per parent: [0,384) iou | [384,512) z_fa | [512,640) z_fb
    __shared__ int s_child[2 * PSUB];
    __shared__ int s_lab[2 * PSUB];
    __shared__ int s_par[PSUB];

    int t = threadIdx.x;
    const int*   e_src   = edges_r + ri * 2 * EPRc;
    const int*   e_child = e_src + EPRc;
    const float* labp    = labels + ri * EPRc;

    const float *rowA0 = U_iou, *rowA1 = U_iou, *rowA2 = U_f;
    const float *rowB0 = U_iou, *rowB1 = U_f;
    if (t < 128) {
        rowA0 = U_iou + t * 256;
        rowA1 = U_iou + (256 + t) * 256;
        rowA2 = U_f + t * 256;
    } else {
        rowB0 = U_iou + t * 256;
        rowB1 = U_f + (t - 128) * 256;
    }

    int pend = min((int)(blockIdx.x + 1) * PPB, NPRc);
    for (int ps = blockIdx.x * PPB; ps < pend; ps += PSUB) {
        int np = min(PSUB, pend - ps);
        __syncthreads();   // protect s_* / gs vs previous sub-batch readers
        if (t < 2 * np) {
            int e = 2 * ps + t;
            s_child[t] = e_child[e];
            s_lab[t]   = (labp[e] != 0.0f) ? 1 : 0;
        }
        if (t < np) s_par[t] = e_src[2 * (ps + t)];
        __syncthreads();

        // build he2_a / he2_b  (h in half 'lab', zero elsewhere)
        for (int idx = t; idx < np * 128; idx += 256) {       // 2*np edges * 64 float4
            int e = idx >> 6, q = idx & 63;
            float4 v = make_float4(0.f, 0.f, 0.f, 0.f);
            if ((q >> 5) == s_lab[e])
                v = ((const float4*)(h + (size_t)s_child[e] * Hh))[q & 31];
            int p = e >> 1, eo = e & 1;
            *((float4*)(gs + p * 768 + 256 + eo * 256) + q) = v;
        }
        __syncthreads();
        // gsum = he2_a + he2_b
        for (int idx = t; idx < np * 64; idx += 256) {
            int p = idx >> 6, q = idx & 63;
            float4 a = *((const float4*)(gs + p * 768 + 256) + q);
            float4 b = *((const float4*)(gs + p * 768 + 512) + q);
            *((float4*)(gs + p * 768) + q) = make_float4(a.x + b.x, a.y + b.y, a.z + b.z, a.w + b.w);
        }
        __syncthreads();

        if (t < 128) {
            float2 a0[PSUB], a1[PSUB], a2[PSUB];
#pragma unroll
            for (int p = 0; p < PSUB; p++) { a0[p] = make_float2(0.f,0.f); a1[p] = make_float2(0.f,0.f); a2[p] = make_float2(0.f,0.f); }
#pragma unroll 1
            for (int k0 = 0; k0 < 256; k0 += 16) {
                float2 w0[8], w1[8], w2[8];
#pragma unroll
                for (int q = 0; q < 4; q++) {
                    float4 v0 = *(const float4*)(rowA0 + k0 + 4 * q);
                    float4 v1 = *(const float4*)(rowA1 + k0 + 4 * q);
                    float4 v2 = *(const float4*)(rowA2 + k0 + 4 * q);
                    w0[2*q] = make_float2(v0.x,v0.y); w0[2*q+1] = make_float2(v0.z,v0.w);
                    w1[2*q] = make_float2(v1.x,v1.y); w1[2*q+1] = make_float2(v1.z,v1.w);
                    w2[2*q] = make_float2(v2.x,v2.y); w2[2*q+1] = make_float2(v2.z,v2.w);
                }
#pragma unroll
                for (int kk = 0; kk < 8; kk++) {
#pragma unroll
                    for (int p = 0; p < PSUB; p++) {
                        float2 g0 = *(const float2*)&gs[p * 768 + k0 + 2 * kk];        // gsum
                        float2 g2 = *(const float2*)&gs[p * 768 + 512 + k0 + 2 * kk];  // he2_b
                        a0[p] = ffma2(w0[kk], g0, a0[p]);
                        a1[p] = ffma2(w1[kk], g0, a1[p]);
                        a2[p] = ffma2(w2[kk], g2, a2[p]);
                    }
                }
            }
#pragma unroll
            for (int p = 0; p < PSUB; p++) {
                epi[p * 640 + t]       = a0[p].x + a0[p].y;   // iou col t
                epi[p * 640 + 256 + t] = a1[p].x + a1[p].y;   // iou col 256+t
                epi[p * 640 + 512 + t] = a2[p].x + a2[p].y;   // z_fb[t]
            }
        } else {
            float2 a0[PSUB], a1[PSUB];
#pragma unroll
            for (int p = 0; p < PSUB; p++) { a0[p] = make_float2(0.f,0.f); a1[p] = make_float2(0.f,0.f); }
#pragma unroll 1
            for (int k0 = 0; k0 < 256; k0 += 16) {
                float2 w0[8], w1[8];
#pragma unroll
                for (int q = 0; q < 4; q++) {
                    float4 v0 = *(const float4*)(rowB0 + k0 + 4 * q);
                    float4 v1 = *(const float4*)(rowB1 + k0 + 4 * q);
                    w0[2*q] = make_float2(v0.x,v0.y); w0[2*q+1] = make_float2(v0.z,v0.w);
                    w1[2*q] = make_float2(v1.x,v1.y); w1[2*q+1] = make_float2(v1.z,v1.w);
                }
#pragma unroll
                for (int kk = 0; kk < 8; kk++) {
#pragma unroll
                    for (int p = 0; p < PSUB; p++) {
                        float2 g0 = *(const float2*)&gs[p * 768 + k0 + 2 * kk];        // gsum
                        float2 g1 = *(const float2*)&gs[p * 768 + 256 + k0 + 2 * kk];  // he2_a
                        a0[p] = ffma2(w0[kk], g0, a0[p]);
                        a1[p] = ffma2(w1[kk], g1, a1[p]);
                    }
                }
            }
#pragma unroll
            for (int p = 0; p < PSUB; p++) {
                epi[p * 640 + t]                = a0[p].x + a0[p].y;   // iou col t
                epi[p * 640 + 384 + (t - 128)]  = a1[p].x + a1[p].y;   // z_fa[t-128]
            }
        }
        __syncthreads();

        // epilogue: f gates, c accumulation, node_update
        for (int idx = t; idx < np * Hh; idx += 256) {
            int pl = idx >> 7, m = idx & 127;
            int par = s_par[pl];
            int cA = s_child[2 * pl], cB = s_child[2 * pl + 1];
            const float* Cp = g_C + (size_t)par * NC;
            float gi = Cp[m]       + epi[pl * 640 + m]       + b_iou[m];
            float go = Cp[128 + m] + epi[pl * 640 + 128 + m] + b_iou[128 + m];
            float gu = Cp[256 + m] + epi[pl * 640 + 256 + m] + b_iou[256 + m];
            float fa = sigf(g_C[(size_t)cA * NC + 384 + m] + epi[pl * 640 + 384 + m] + b_f[m]);
            float fb = sigf(g_C[(size_t)cB * NC + 384 + m] + epi[pl * 640 + 512 + m] + b_f[m]);
            float ca = g_c[(size_t)cA * Hh + m]; ca = fminf(fmaxf(ca, -1e14f), 1e14f);
            float cb = g_c[(size_t)cB * Hh + m]; cb = fminf(fmaxf(cb, -1e14f), 1e14f);
            float ct = sigf(gi) * tanhf(gu) + fa * ca + fb * cb;
            g_c[(size_t)par * Hh + m] = ct;
            h[(size_t)par * Hh + m]   = sigf(go) * tanhf(ct);
        }
    }
}

// ---------------------------------------------------------------------------
extern "C" void kernel_launch(void* const* d_in, const int* in_sizes, int n_in,
                              void* d_out, int out_size) {
    const float* x      = (const float*)d_in[0];
    const float* labels = (const float*)d_in[1];   // [15,6000,1]
    const float* W_iou  = (const float*)d_in[2];
    const float* W_f    = (const float*)d_in[3];
    const float* b_iou  = (const float*)d_in[4];
    const float* b_f    = (const float*)d_in[5];
    const float* U_iou  = (const float*)d_in[6];
    const float* U_f    = (const float*)d_in[7];
    const int*   edges  = (const int*)d_in[8];     // [15,2,6000]
    const int*   order0 = (const int*)d_in[9];
    float* h = (float*)d_out;                      // h lives directly in d_out

    k_pre<<<148, 256>>>(x, W_iou, W_f);
    k_round0<<<(NPRc * Hh + 255) / 256, 256>>>(h, order0, b_iou);
    for (int ri = 0; ri < 15; ri++)
        k_round<<<148, 256>>>(ri, h, U_iou, U_f, b_iou, b_f, edges, labels);
}

// round 4
// speedup vs baseline: 1.7471x; 1.7420x over previous
#include <cuda_runtime.h>
#include <math.h>

#define Hh   128
#define NPRc 3000
#define EPRc 6000
#define NTOT 48000
#define NCc  512     // C columns: [0,384) iou_x, [384,512) wf_x

// static scratch (no allocations allowed)
__device__ float g_C[(size_t)NTOT * NCc];   // 98.3 MB
__device__ float g_c[(size_t)NTOT * Hh];    // 24.6 MB

union F2U { float2 f; unsigned long long u; };
__device__ __forceinline__ float2 ffma2(float2 a, float2 b, float2 c) {
    F2U A, B, C2, D;
    A.f = a; B.f = b; C2.f = c;
    asm("fma.rn.f32x2 %0, %1, %2, %3;" : "=l"(D.u) : "l"(A.u), "l"(B.u), "l"(C2.u));
    return D.f;
}
__device__ __forceinline__ float2 spl(float b) { return make_float2(b, b); }
__device__ __forceinline__ float sigf(float x) { return 1.0f / (1.0f + expf(-x)); }

// ---------------------------------------------------------------------------
// k_pre: C[n][0:384] = x @ W_iou^T ; C[n][384:512] = x @ W_f^T
// Tiled GEMM: 32 rows x 512 cols per block, K=128. grid 1500, 2 blocks/SM.
// smem floats: A[128*36] @0 | Bs[2*4*512] @4608 | xs[32*132] @8704 = 12928
// ---------------------------------------------------------------------------
#define PRE_SMEMB (12928 * 4)

__global__ __launch_bounds__(256, 2) void k_pre(const float* __restrict__ x,
        const float* __restrict__ W_iou, const float* __restrict__ W_f) {
    extern __shared__ float sm[];
    float* A  = sm;          // [k][row], stride 36
    float* Bs = sm + 4608;   // [buf][kk][512]
    float* xs = sm + 8704;   // [row][132] staging
    int t  = threadIdx.x;
    int r0 = blockIdx.x * 32;

#pragma unroll
    for (int j = 0; j < 4; j++) {                      // stage x coalesced
        int f = t + 256 * j, row = f >> 5, q = f & 31;
        *(float4*)&xs[row * 132 + 4 * q] = *((const float4*)(x + (size_t)(r0 + row) * 128) + q);
    }
    __syncthreads();
#pragma unroll
    for (int j = 0; j < 4; j++) {                      // transpose -> A[k][row]
        int f = t + 256 * j, row = f & 31, q = f >> 5;
        float4 v = *(const float4*)&xs[row * 132 + 4 * q];
        A[(4 * q + 0) * 36 + row] = v.x; A[(4 * q + 1) * 36 + row] = v.y;
        A[(4 * q + 2) * 36 + row] = v.z; A[(4 * q + 3) * 36 + row] = v.w;
    }
#pragma unroll
    for (int j = 0; j < 2; j++) {                      // B chunk 0 (k=0..3)
        int row = t + 256 * j;
        const float* src = (row < 384) ? (W_iou + row * 128) : (W_f + (row - 384) * 128);
        float4 v = *(const float4*)src;
        Bs[row] = v.x; Bs[512 + row] = v.y; Bs[1024 + row] = v.z; Bs[1536 + row] = v.w;
    }
    __syncthreads();

    int ct = t & 127;            // cols ct, 128+ct, 256+ct, 384+ct
    int rb = (t >> 7) * 16;      // 16 rows
    float2 acc[4][8];
#pragma unroll
    for (int cc = 0; cc < 4; cc++)
#pragma unroll
        for (int r = 0; r < 8; r++) acc[cc][r] = make_float2(0.f, 0.f);

#pragma unroll 1
    for (int c = 0; c < 32; c++) {                     // 32 chunks x 4 k
        float4 nb0, nb1;
        if (c < 31) {
            int row0 = t, row1 = t + 256;
            const float* s0 = (row0 < 384) ? (W_iou + row0 * 128) : (W_f + (row0 - 384) * 128);
            const float* s1 = (row1 < 384) ? (W_iou + row1 * 128) : (W_f + (row1 - 384) * 128);
            nb0 = *(const float4*)(s0 + (c + 1) * 4);
            nb1 = *(const float4*)(s1 + (c + 1) * 4);
        }
        const float* Bb = Bs + (c & 1) * 2048;
#pragma unroll
        for (int kk = 0; kk < 4; kk++) {
            int kg = c * 4 + kk;
            float2 b0 = spl(Bb[kk * 512 + ct]);
            float2 b1 = spl(Bb[kk * 512 + 128 + ct]);
            float2 b2 = spl(Bb[kk * 512 + 256 + ct]);
            float2 b3 = spl(Bb[kk * 512 + 384 + ct]);
            const float* ap = A + kg * 36 + rb;
#pragma unroll
            for (int g4 = 0; g4 < 4; g4++) {
                float4 av = *(const float4*)(ap + 4 * g4);
                float2 p0 = make_float2(av.x, av.y), p1 = make_float2(av.z, av.w);
                acc[0][2*g4]   = ffma2(b0, p0, acc[0][2*g4]);
                acc[0][2*g4+1] = ffma2(b0, p1, acc[0][2*g4+1]);
                acc[1][2*g4]   = ffma2(b1, p0, acc[1][2*g4]);
                acc[1][2*g4+1] = ffma2(b1, p1, acc[1][2*g4+1]);
                acc[2][2*g4]   = ffma2(b2, p0, acc[2][2*g4]);
                acc[2][2*g4+1] = ffma2(b2, p1, acc[2][2*g4+1]);
                acc[3][2*g4]   = ffma2(b3, p0, acc[3][2*g4]);
                acc[3][2*g4+1] = ffma2(b3, p1, acc[3][2*g4+1]);
            }
        }
        if (c < 31) {
            float* d = Bs + ((c + 1) & 1) * 2048;
            int row0 = t, row1 = t + 256;
            d[row0] = nb0.x; d[512 + row0] = nb0.y; d[1024 + row0] = nb0.z; d[1536 + row0] = nb0.w;
            d[row1] = nb1.x; d[512 + row1] = nb1.y; d[1024 + row1] = nb1.z; d[1536 + row1] = nb1.w;
            __syncthreads();
        }
    }
#pragma unroll
    for (int cc = 0; cc < 4; cc++) {                   // grid*32 == 48000, no guard
        int col = ct + 128 * cc;
#pragma unroll
        for (int r = 0; r < 8; r++) {
            int row = r0 + rb + 2 * r;
            g_C[(size_t)row * NCc + col]       = acc[cc][r].x;
            g_C[(size_t)(row + 1) * NCc + col] = acc[cc][r].y;
        }
    }
}

// ---------------------------------------------------------------------------
// Round 0: leaves. iou_mid = 0, c = 0.
// ---------------------------------------------------------------------------
__global__ __launch_bounds__(256) void k_round0(float* __restrict__ h,
                                                const int* __restrict__ order0,
                                                const float* __restrict__ b_iou) {
    int idx = blockIdx.x * 256 + threadIdx.x;
    if (idx >= NPRc * Hh) return;
    int j = idx >> 7, m = idx & 127;
    int node = order0[j];
    const float* Cp = g_C + (size_t)node * NCc;
    float gi = Cp[m]       + b_iou[m];
    float go = Cp[128 + m] + b_iou[128 + m];
    float gu = Cp[256 + m] + b_iou[256 + m];
    float ct = sigf(gi) * tanhf(gu);
    g_c[(size_t)node * Hh + m] = ct;
    h[(size_t)node * Hh + m]   = sigf(go) * tanhf(ct);
}

// ---------------------------------------------------------------------------
// One topological round, fused tiled GEMM. grid 148 x 256 thr; ~21-parent tile
// padded to 24. A-tile [stream][k][24] smem: s0=gsum, s1=he2_a, s2=he2_b.
// B = 512 weight rows (U_iou 384 + U_f 128) double-buffered 8-k chunks.
// Thread (ct = t&127, pb = (t>>7)*12): 5 col-streams x 12 parents.
// smem floats: As 18432 @0 | Bs 8192 @18432 (hs[48*132] aliases Bs;
// epi[24*640] aliases As after GEMM). total 26624.
// ---------------------------------------------------------------------------
#define RND_SMEMB (26624 * 4)

__global__ __launch_bounds__(256) void k_round(int ri, float* __restrict__ h,
        const float* __restrict__ U_iou, const float* __restrict__ U_f,
        const float* __restrict__ b_iou, const float* __restrict__ b_f,
        const int* __restrict__ edges_r, const float* __restrict__ labels) {
    extern __shared__ float sm[];
    float* As  = sm;            // 3*256*24
    float* Bs  = sm + 18432;    // 2*8*512
    float* hs  = Bs;            // staging alias (48*132 = 6336 <= 8192)
    float* epi = sm;            // alias after GEMM (24*640 = 15360 <= 18432)
    __shared__ int s_child[48], s_lab[48], s_par[24];

    int t  = threadIdx.x;
    int p0 = ((int)blockIdx.x * NPRc) / 148;
    int p1 = (((int)blockIdx.x + 1) * NPRc) / 148;
    int np = p1 - p0;           // 20 or 21

    const int*   e_src   = edges_r + ri * 2 * EPRc;
    const int*   e_child = e_src + EPRc;
    const float* labp    = labels + ri * EPRc;

    if (t < 48) {
        int ok = t < 2 * np;
        int e = 2 * p0 + t;
        s_child[t] = ok ? e_child[e] : 0;
        s_lab[t]   = ok ? (labp[e] != 0.0f ? 1 : 0) : 0;
    }
    if (t >= 64 && t < 88) {
        int pp = t - 64;
        s_par[pp] = (pp < np) ? e_src[2 * (p0 + pp)] : 0;
    }
    __syncthreads();

    // stage 48 child h-rows coalesced
#pragma unroll
    for (int j = 0; j < 6; j++) {
        int f = t + 256 * j, e = f >> 5, q = f & 31;
        *(float4*)&hs[e * 132 + 4 * q] = *((const float4*)(h + (size_t)s_child[e] * Hh) + q);
    }
    __syncthreads();
    // scatter into As streams 1,2 with zero complement (k-major, stride 24)
#pragma unroll
    for (int j = 0; j < 6; j++) {
        int f = t + 256 * j, e = f % 48, q = f / 48;
        float4 v = *(const float4*)&hs[e * 132 + 4 * q];
        int p = e >> 1, eo = e & 1, lab = s_lab[e];
        int bh = ((1 + eo) * 256 + lab * 128 + 4 * q) * 24 + p;
        int bz = ((1 + eo) * 256 + (1 - lab) * 128 + 4 * q) * 24 + p;
        As[bh] = v.x; As[bh + 24] = v.y; As[bh + 48] = v.z; As[bh + 72] = v.w;
        As[bz] = 0.f; As[bz + 24] = 0.f; As[bz + 48] = 0.f; As[bz + 72] = 0.f;
    }
    __syncthreads();            // hs (Bs alias) dead from here
    // stream0 = gsum = he2_a + he2_b
#pragma unroll
    for (int j = 0; j < 6; j++) {
        int f = t + 256 * j, k = f / 6, pq = (f % 6) * 4;
        float4 a = *(const float4*)&As[(256 + k) * 24 + pq];
        float4 b = *(const float4*)&As[(512 + k) * 24 + pq];
        *(float4*)&As[k * 24 + pq] = make_float4(a.x + b.x, a.y + b.y, a.z + b.z, a.w + b.w);
    }
    // B chunk 0 (k=0..7)
#pragma unroll
    for (int j = 0; j < 4; j++) {
        int f = t + 256 * j, row = f >> 1, half = f & 1;
        const float* src = (row < 384) ? (U_iou + row * 256) : (U_f + (row - 384) * 256);
        float4 v = *(const float4*)(src + half * 4);
        float* d = Bs + (half * 4) * 512 + row;
        d[0] = v.x; d[512] = v.y; d[1024] = v.z; d[1536] = v.w;
    }
    __syncthreads();

    int ct = t & 127;
    int pb = (t >> 7) * 12;
    const float* Ag = As;
    const float* Aa = As + 6144;
    const float* Ab = As + 12288;
    float2 acc[5][6];
#pragma unroll
    for (int s5 = 0; s5 < 5; s5++)
#pragma unroll
        for (int pr = 0; pr < 6; pr++) acc[s5][pr] = make_float2(0.f, 0.f);

#pragma unroll 1
    for (int c = 0; c < 32; c++) {                     // 32 chunks x 8 k
        float4 nb[4];
        if (c < 31) {
#pragma unroll
            for (int j = 0; j < 4; j++) {
                int f = t + 256 * j, row = f >> 1, half = f & 1;
                const float* src = (row < 384) ? (U_iou + row * 256) : (U_f + (row - 384) * 256);
                nb[j] = *(const float4*)(src + (c + 1) * 8 + half * 4);
            }
        }
        const float* Bb = Bs + (c & 1) * 4096;
#pragma unroll
        for (int kk = 0; kk < 8; kk++) {
            int kg = c * 8 + kk;
            float2 b0 = spl(Bb[kk * 512 + ct]);
            float2 b1 = spl(Bb[kk * 512 + 128 + ct]);
            float2 b2 = spl(Bb[kk * 512 + 256 + ct]);
            float2 b3 = spl(Bb[kk * 512 + 384 + ct]);
#pragma unroll
            for (int g4 = 0; g4 < 3; g4++) {           // 12 parents = 3 float4
                int off = kg * 24 + pb + 4 * g4;
                float4 g = *(const float4*)(Ag + off);
                float2 q0 = make_float2(g.x, g.y), q1 = make_float2(g.z, g.w);
                acc[0][2*g4]   = ffma2(b0, q0, acc[0][2*g4]);
                acc[0][2*g4+1] = ffma2(b0, q1, acc[0][2*g4+1]);
                acc[1][2*g4]   = ffma2(b1, q0, acc[1][2*g4]);
                acc[1][2*g4+1] = ffma2(b1, q1, acc[1][2*g4+1]);
                acc[2][2*g4]   = ffma2(b2, q0, acc[2][2*g4]);
                acc[2][2*g4+1] = ffma2(b2, q1, acc[2][2*g4+1]);
                float4 a = *(const float4*)(Aa + off);
                acc[3][2*g4]   = ffma2(b3, make_float2(a.x, a.y), acc[3][2*g4]);
                acc[3][2*g4+1] = ffma2(b3, make_float2(a.z, a.w), acc[3][2*g4+1]);
                float4 hb = *(const float4*)(Ab + off);
                acc[4][2*g4]   = ffma2(b3, make_float2(hb.x, hb.y), acc[4][2*g4]);
                acc[4][2*g4+1] = ffma2(b3, make_float2(hb.z, hb.w), acc[4][2*g4+1]);
            }
        }
        if (c < 31) {
            float* d = Bs + ((c + 1) & 1) * 4096;
#pragma unroll
            for (int j = 0; j < 4; j++) {
                int f = t + 256 * j, row = f >> 1, half = f & 1;
                float* dd = d + (half * 4) * 512 + row;
                dd[0] = nb[j].x; dd[512] = nb[j].y; dd[1024] = nb[j].z; dd[1536] = nb[j].w;
            }
            __syncthreads();
        }
    }
    __syncthreads();            // all GEMM reads of As done before epi overwrite

#pragma unroll
    for (int pr = 0; pr < 6; pr++) {
        int p = pb + 2 * pr;
        epi[p * 640 + ct]             = acc[0][pr].x;  epi[(p + 1) * 640 + ct]             = acc[0][pr].y;
        epi[p * 640 + 128 + ct]       = acc[1][pr].x;  epi[(p + 1) * 640 + 128 + ct]       = acc[1][pr].y;
        epi[p * 640 + 256 + ct]       = acc[2][pr].x;  epi[(p + 1) * 640 + 256 + ct]       = acc[2][pr].y;
        epi[p * 640 + 384 + ct]       = acc[3][pr].x;  epi[(p + 1) * 640 + 384 + ct]       = acc[3][pr].y;
        epi[p * 640 + 512 + ct]       = acc[4][pr].x;  epi[(p + 1) * 640 + 512 + ct]       = acc[4][pr].y;
    }
    __syncthreads();

    // epilogue: f gates, c accumulation, node_update
    for (int idx = t; idx < np * Hh; idx += 256) {
        int pl = idx >> 7, m = idx & 127;
        int par = s_par[pl];
        int cA = s_child[2 * pl], cB = s_child[2 * pl + 1];
        const float* Cp = g_C + (size_t)par * NCc;
        float gi = Cp[m]       + epi[pl * 640 + m]       + b_iou[m];
        float go = Cp[128 + m] + epi[pl * 640 + 128 + m] + b_iou[128 + m];
        float gu = Cp[256 + m] + epi[pl * 640 + 256 + m] + b_iou[256 + m];
        float fa = sigf(g_C[(size_t)cA * NCc + 384 + m] + epi[pl * 640 + 384 + m] + b_f[m]);
        float fb = sigf(g_C[(size_t)cB * NCc + 384 + m] + epi[pl * 640 + 512 + m] + b_f[m]);
        float ca = g_c[(size_t)cA * Hh + m]; ca = fminf(fmaxf(ca, -1e14f), 1e14f);
        float cb = g_c[(size_t)cB * Hh + m]; cb = fminf(fmaxf(cb, -1e14f), 1e14f);
        float ct2 = sigf(gi) * tanhf(gu) + fa * ca + fb * cb;
        g_c[(size_t)par * Hh + m] = ct2;
        h[(size_t)par * Hh + m]   = sigf(go) * tanhf(ct2);
    }
}

// ---------------------------------------------------------------------------
extern "C" void kernel_launch(void* const* d_in, const int* in_sizes, int n_in,
                              void* d_out, int out_size) {
    const float* x      = (const float*)d_in[0];
    const float* labels = (const float*)d_in[1];   // [15,6000,1]
    const float* W_iou  = (const float*)d_in[2];
    const float* W_f    = (const float*)d_in[3];
    const float* b_iou  = (const float*)d_in[4];
    const float* b_f    = (const float*)d_in[5];
    const float* U_iou  = (const float*)d_in[6];
    const float* U_f    = (const float*)d_in[7];
    const int*   edges  = (const int*)d_in[8];     // [15,2,6000]
    const int*   order0 = (const int*)d_in[9];
    float* h = (float*)d_out;                      // h lives directly in d_out

    cudaFuncSetAttribute(k_pre,   cudaFuncAttributeMaxDynamicSharedMemorySize, PRE_SMEMB);
    cudaFuncSetAttribute(k_round, cudaFuncAttributeMaxDynamicSharedMemorySize, RND_SMEMB);

    k_pre<<<1500, 256, PRE_SMEMB>>>(x, W_iou, W_f);
    k_round0<<<(NPRc * Hh + 255) / 256, 256>>>(h, order0, b_iou);
    for (int ri = 0; ri < 15; ri++)
        k_round<<<148, 256, RND_SMEMB>>>(ri, h, U_iou, U_f, b_iou, b_f, edges, labels);
}

// round 6
// speedup vs baseline: 2.5201x; 1.4424x over previous
#include <cuda_runtime.h>
#include <math.h>

#define Hh   128
#define NPRc 3000
#define EPRc 6000
#define NTOT 48000
#define NCc  512     // C columns: [0,384) iou_x, [384,512) wf_x

// static scratch (no allocations allowed)
__device__ float g_C[(size_t)NTOT * NCc];   // 98.3 MB
__device__ float g_c[(size_t)NTOT * Hh];    // 24.6 MB
__device__ float g_Ut[256 * 512];           // U^T: [k][row]  (row<384: U_iou, else U_f)
__device__ float g_Wt[128 * 512];           // W^T: [k][row]  (row<384: W_iou, else W_f)

union F2U { float2 f; unsigned long long u; };
__device__ __forceinline__ float2 ffma2(float2 a, float2 b, float2 c) {
    F2U A, B, C2, D;
    A.f = a; B.f = b; C2.f = c;
    asm("fma.rn.f32x2 %0, %1, %2, %3;" : "=l"(D.u) : "l"(A.u), "l"(B.u), "l"(C2.u));
    return D.f;
}
__device__ __forceinline__ float2 spl(float b) { return make_float2(b, b); }
__device__ __forceinline__ float sigf(float x) { return 1.0f / (1.0f + expf(-x)); }

// ---------------------------------------------------------------------------
// One-shot weight transposes (writes coalesced)
// ---------------------------------------------------------------------------
__global__ __launch_bounds__(256) void k_transU(const float* __restrict__ U_iou,
                                                const float* __restrict__ U_f) {
    int idx = blockIdx.x * 256 + threadIdx.x;          // grid 512 -> 131072
    int k = idx >> 9, row = idx & 511;
    g_Ut[idx] = (row < 384) ? U_iou[row * 256 + k] : U_f[(row - 384) * 256 + k];
}
__global__ __launch_bounds__(256) void k_transW(const float* __restrict__ W_iou,
                                                const float* __restrict__ W_f) {
    int idx = blockIdx.x * 256 + threadIdx.x;          // grid 256 -> 65536
    int k = idx >> 9, row = idx & 511;
    g_Wt[idx] = (row < 384) ? W_iou[row * 128 + k] : W_f[(row - 384) * 128 + k];
}

// ---------------------------------------------------------------------------
// k_pre: C[n][0:384] = x @ W_iou^T ; C[n][384:512] = x @ W_f^T
// Tiled GEMM: 32 rows x 512 cols per block, K=128. grid 1500, 2 blocks/SM.
// B loads coalesced from g_Wt. 16 chunks x 8 k, double-buffered.
// smem floats: A[128*36] @0 | Bs[2*8*512] @4608 | xs[32*132] @12800 = 17024
// ---------------------------------------------------------------------------
#define PRE_SMEMB (17024 * 4)

__global__ __launch_bounds__(256, 2) void k_pre(const float* __restrict__ x) {
    extern __shared__ float sm[];
    float* A  = sm;           // [k][row], stride 36
    float* Bs = sm + 4608;    // [buf][kk][512]
    float* xs = sm + 12800;   // [row][132]
    int t  = threadIdx.x;
    int r0 = blockIdx.x * 32;

#pragma unroll
    for (int j = 0; j < 4; j++) {                      // stage x coalesced
        int f = t + 256 * j, row = f >> 5, q = f & 31;
        *(float4*)&xs[row * 132 + 4 * q] = *((const float4*)(x + (size_t)(r0 + row) * 128) + q);
    }
    __syncthreads();
#pragma unroll
    for (int j = 0; j < 4; j++) {                      // transpose -> A[k][row]
        int f = t + 256 * j, row = f & 31, q = f >> 5;
        float4 v = *(const float4*)&xs[row * 132 + 4 * q];
        A[(4 * q + 0) * 36 + row] = v.x; A[(4 * q + 1) * 36 + row] = v.y;
        A[(4 * q + 2) * 36 + row] = v.z; A[(4 * q + 3) * 36 + row] = v.w;
    }
#pragma unroll
    for (int j = 0; j < 4; j++) {                      // B chunk 0 (k=0..7), coalesced
        int f = t + 256 * j, ks = f >> 7, c4 = (f & 127) * 4;
        *(float4*)&Bs[ks * 512 + c4] = *(const float4*)&g_Wt[ks * 512 + c4];
    }
    __syncthreads();

    int ct = t & 127;            // cols ct, 128+ct, 256+ct, 384+ct
    int rb = (t >> 7) * 16;      // 16 rows (48B-aligned: rb in {0,16})
    float2 acc[4][8];
#pragma unroll
    for (int cc = 0; cc < 4; cc++)
#pragma unroll
        for (int r = 0; r < 8; r++) acc[cc][r] = make_float2(0.f, 0.f);

#pragma unroll 1
    for (int c = 0; c < 16; c++) {                     // 16 chunks x 8 k
        float4 nb[4];
        if (c < 15) {
#pragma unroll
            for (int j = 0; j < 4; j++) {
                int f = t + 256 * j, ks = f >> 7, c4 = (f & 127) * 4;
                nb[j] = *(const float4*)&g_Wt[((c + 1) * 8 + ks) * 512 + c4];
            }
        }
        const float* Bb = Bs + (c & 1) * 4096;
#pragma unroll
        for (int kk = 0; kk < 8; kk++) {
            int kg = c * 8 + kk;
            float2 b0 = spl(Bb[kk * 512 + ct]);
            float2 b1 = spl(Bb[kk * 512 + 128 + ct]);
            float2 b2 = spl(Bb[kk * 512 + 256 + ct]);
            float2 b3 = spl(Bb[kk * 512 + 384 + ct]);
            const float* ap = A + kg * 36 + rb;
#pragma unroll
            for (int g4 = 0; g4 < 4; g4++) {
                float4 av = *(const float4*)(ap + 4 * g4);
                float2 p0 = make_float2(av.x, av.y), p1 = make_float2(av.z, av.w);
                acc[0][2*g4]   = ffma2(b0, p0, acc[0][2*g4]);
                acc[0][2*g4+1] = ffma2(b0, p1, acc[0][2*g4+1]);
                acc[1][2*g4]   = ffma2(b1, p0, acc[1][2*g4]);
                acc[1][2*g4+1] = ffma2(b1, p1, acc[1][2*g4+1]);
                acc[2][2*g4]   = ffma2(b2, p0, acc[2][2*g4]);
                acc[2][2*g4+1] = ffma2(b2, p1, acc[2][2*g4+1]);
                acc[3][2*g4]   = ffma2(b3, p0, acc[3][2*g4]);
                acc[3][2*g4+1] = ffma2(b3, p1, acc[3][2*g4+1]);
            }
        }
        if (c < 15) {
            float* d = Bs + ((c + 1) & 1) * 4096;
#pragma unroll
            for (int j = 0; j < 4; j++) {
                int f = t + 256 * j, ks = f >> 7, c4 = (f & 127) * 4;
                *(float4*)&d[ks * 512 + c4] = nb[j];
            }
            __syncthreads();
        }
    }
#pragma unroll
    for (int cc = 0; cc < 4; cc++) {                   // grid*32 == 48000, no guard
        int col = ct + 128 * cc;
#pragma unroll
        for (int r = 0; r < 8; r++) {
            int row = r0 + rb + 2 * r;
            g_C[(size_t)row * NCc + col]       = acc[cc][r].x;
            g_C[(size_t)(row + 1) * NCc + col] = acc[cc][r].y;
        }
    }
}

// ---------------------------------------------------------------------------
// Round 0: leaves. iou_mid = 0, c = 0.
// ---------------------------------------------------------------------------
__global__ __launch_bounds__(256) void k_round0(float* __restrict__ h,
                                                const int* __restrict__ order0,
                                                const float* __restrict__ b_iou) {
    int idx = blockIdx.x * 256 + threadIdx.x;
    if (idx >= NPRc * Hh) return;
    int j = idx >> 7, m = idx & 127;
    int node = order0[j];
    const float* Cp = g_C + (size_t)node * NCc;
    float gi = Cp[m]       + b_iou[m];
    float go = Cp[128 + m] + b_iou[128 + m];
    float gu = Cp[256 + m] + b_iou[256 + m];
    float ct = sigf(gi) * tanhf(gu);
    g_c[(size_t)node * Hh + m] = ct;
    h[(size_t)node * Hh + m]   = sigf(go) * tanhf(ct);
}

// ---------------------------------------------------------------------------
// One topological round. grid 148 x 512 thr (16 warps/SM); ~21-parent tile
// padded to 24. A-tile [stream][k][24]: s0=gsum, s1=he2_a, s2=he2_b.
// B = 512 weight rows, coalesced from g_Ut, double-buffered 16-k chunks.
// Thread (ct = t&127, pg = (t>>7)*6): 5 col-streams x 6 parents.
// A-tile reads are float2 (8B-aligned: pg even) — pg=6,18 are NOT 16B-aligned,
// float4 here traps with misaligned-address.
// smem floats: As 18432 @0 | Bs 16384 @18432 (hs aliases Bs; epi aliases As).
// ---------------------------------------------------------------------------
#define RND_SMEMB (34816 * 4)

__global__ __launch_bounds__(512) void k_round(int ri, float* __restrict__ h,
        const float* __restrict__ b_iou, const float* __restrict__ b_f,
        const int* __restrict__ edges_r, const float* __restrict__ labels) {
    extern __shared__ float sm[];
    float* As  = sm;            // 3*256*24
    float* Bs  = sm + 18432;    // 2*16*512
    float* hs  = Bs;            // staging alias (48*132 = 6336 <= 16384)
    float* epi = sm;            // alias after GEMM (24*640 = 15360 <= 18432)
    __shared__ int s_child[48], s_lab[48], s_par[24];

    int t  = threadIdx.x;
    int p0 = ((int)blockIdx.x * NPRc) / 148;
    int p1 = (((int)blockIdx.x + 1) * NPRc) / 148;
    int np = p1 - p0;           // 20 or 21

    const int*   e_src   = edges_r + ri * 2 * EPRc;
    const int*   e_child = e_src + EPRc;
    const float* labp    = labels + ri * EPRc;

    if (t < 48) {
        int ok = t < 2 * np;
        int e = 2 * p0 + t;
        s_child[t] = ok ? e_child[e] : 0;
        s_lab[t]   = ok ? (labp[e] != 0.0f ? 1 : 0) : 0;
    }
    if (t >= 64 && t < 88) {
        int pp = t - 64;
        s_par[pp] = (pp < np) ? e_src[2 * (p0 + pp)] : 0;
    }
    __syncthreads();

    // stage 48 child h-rows coalesced
#pragma unroll
    for (int j = 0; j < 3; j++) {
        int f = t + 512 * j, e = f >> 5, q = f & 31;
        *(float4*)&hs[e * 132 + 4 * q] = *((const float4*)(h + (size_t)s_child[e] * Hh) + q);
    }
    __syncthreads();
    // scatter into As streams 1,2 with zero complement (k-major, stride 24)
#pragma unroll
    for (int j = 0; j < 3; j++) {
        int f = t + 512 * j, e = f % 48, q = f / 48;
        float4 v = *(const float4*)&hs[e * 132 + 4 * q];
        int p = e >> 1, eo = e & 1, lab = s_lab[e];
        int bh = ((1 + eo) * 256 + lab * 128 + 4 * q) * 24 + p;
        int bz = ((1 + eo) * 256 + (1 - lab) * 128 + 4 * q) * 24 + p;
        As[bh] = v.x; As[bh + 24] = v.y; As[bh + 48] = v.z; As[bh + 72] = v.w;
        As[bz] = 0.f; As[bz + 24] = 0.f; As[bz + 48] = 0.f; As[bz + 72] = 0.f;
    }
    __syncthreads();            // hs (Bs alias) dead from here
    // stream0 = gsum = he2_a + he2_b
#pragma unroll
    for (int j = 0; j < 3; j++) {
        int f = t + 512 * j, k = f / 6, pq = (f % 6) * 4;
        float4 a = *(const float4*)&As[(256 + k) * 24 + pq];
        float4 b = *(const float4*)&As[(512 + k) * 24 + pq];
        *(float4*)&As[k * 24 + pq] = make_float4(a.x + b.x, a.y + b.y, a.z + b.z, a.w + b.w);
    }
    // B chunk 0 (k=0..15), coalesced
#pragma unroll
    for (int j = 0; j < 4; j++) {
        int f = t + 512 * j, ks = f >> 7, c4 = (f & 127) * 4;
        *(float4*)&Bs[ks * 512 + c4] = *(const float4*)&g_Ut[ks * 512 + c4];
    }
    __syncthreads();

    int ct = t & 127;
    int pg = (t >> 7) * 6;
    const float* Ag = As;
    const float* Aa = As + 6144;
    const float* Ab = As + 12288;
    float2 acc[5][3];
#pragma unroll
    for (int s5 = 0; s5 < 5; s5++)
#pragma unroll
        for (int pr = 0; pr < 3; pr++) acc[s5][pr] = make_float2(0.f, 0.f);

#pragma unroll 1
    for (int c = 0; c < 16; c++) {                     // 16 chunks x 16 k
        float4 nb[4];
        if (c < 15) {
#pragma unroll
            for (int j = 0; j < 4; j++) {
                int f = t + 512 * j, ks = f >> 7, c4 = (f & 127) * 4;
                nb[j] = *(const float4*)&g_Ut[((c + 1) * 16 + ks) * 512 + c4];
            }
        }
        const float* Bb = Bs + (c & 1) * 8192;
#pragma unroll
        for (int kk = 0; kk < 16; kk++) {
            int kg = c * 16 + kk;
            float2 b0 = spl(Bb[kk * 512 + ct]);
            float2 b1 = spl(Bb[kk * 512 + 128 + ct]);
            float2 b2 = spl(Bb[kk * 512 + 256 + ct]);
            float2 b3 = spl(Bb[kk * 512 + 384 + ct]);
            int off = kg * 24 + pg;
            float2 q0 = *(const float2*)(Ag + off);
            float2 q1 = *(const float2*)(Ag + off + 2);
            float2 q2 = *(const float2*)(Ag + off + 4);
            acc[0][0] = ffma2(b0, q0, acc[0][0]);
            acc[0][1] = ffma2(b0, q1, acc[0][1]);
            acc[0][2] = ffma2(b0, q2, acc[0][2]);
            acc[1][0] = ffma2(b1, q0, acc[1][0]);
            acc[1][1] = ffma2(b1, q1, acc[1][1]);
            acc[1][2] = ffma2(b1, q2, acc[1][2]);
            acc[2][0] = ffma2(b2, q0, acc[2][0]);
            acc[2][1] = ffma2(b2, q1, acc[2][1]);
            acc[2][2] = ffma2(b2, q2, acc[2][2]);
            float2 a0 = *(const float2*)(Aa + off);
            float2 a1 = *(const float2*)(Aa + off + 2);
            float2 a2 = *(const float2*)(Aa + off + 4);
            acc[3][0] = ffma2(b3, a0, acc[3][0]);
            acc[3][1] = ffma2(b3, a1, acc[3][1]);
            acc[3][2] = ffma2(b3, a2, acc[3][2]);
            float2 h0 = *(const float2*)(Ab + off);
            float2 h1 = *(const float2*)(Ab + off + 2);
            float2 h2 = *(const float2*)(Ab + off + 4);
            acc[4][0] = ffma2(b3, h0, acc[4][0]);
            acc[4][1] = ffma2(b3, h1, acc[4][1]);
            acc[4][2] = ffma2(b3, h2, acc[4][2]);
        }
        if (c < 15) {
            float* d = Bs + ((c + 1) & 1) * 8192;
#pragma unroll
            for (int j = 0; j < 4; j++) {
                int f = t + 512 * j, ks = f >> 7, c4 = (f & 127) * 4;
                *(float4*)&d[ks * 512 + c4] = nb[j];
            }
            __syncthreads();
        }
    }
    __syncthreads();            // all GEMM reads of As done before epi overwrite

#pragma unroll
    for (int pr = 0; pr < 3; pr++) {
        int p = pg + 2 * pr;
        epi[p * 640 + ct]       = acc[0][pr].x;  epi[(p + 1) * 640 + ct]       = acc[0][pr].y;
        epi[p * 640 + 128 + ct] = acc[1][pr].x;  epi[(p + 1) * 640 + 128 + ct] = acc[1][pr].y;
        epi[p * 640 + 256 + ct] = acc[2][pr].x;  epi[(p + 1) * 640 + 256 + ct] = acc[2][pr].y;
        epi[p * 640 + 384 + ct] = acc[3][pr].x;  epi[(p + 1) * 640 + 384 + ct] = acc[3][pr].y;
        epi[p * 640 + 512 + ct] = acc[4][pr].x;  epi[(p + 1) * 640 + 512 + ct] = acc[4][pr].y;
    }
    __syncthreads();

    // epilogue: f gates, c accumulation, node_update
    for (int idx = t; idx < np * Hh; idx += 512) {
        int pl = idx >> 7, m = idx & 127;
        int par = s_par[pl];
        int cA = s_child[2 * pl], cB = s_child[2 * pl + 1];
        const float* Cp = g_C + (size_t)par * NCc;
        float gi = Cp[m]       + epi[pl * 640 + m]       + b_iou[m];
        float go = Cp[128 + m] + epi[pl * 640 + 128 + m] + b_iou[128 + m];
        float gu = Cp[256 + m] + epi[pl * 640 + 256 + m] + b_iou[256 + m];
        float fa = sigf(g_C[(size_t)cA * NCc + 384 + m] + epi[pl * 640 + 384 + m] + b_f[m]);
        float fb = sigf(g_C[(size_t)cB * NCc + 384 + m] + epi[pl * 640 + 512 + m] + b_f[m]);
        float ca = g_c[(size_t)cA * Hh + m]; ca = fminf(fmaxf(ca, -1e14f), 1e14f);
        float cb = g_c[(size_t)cB * Hh + m]; cb = fminf(fmaxf(cb, -1e14f), 1e14f);
        float ct2 = sigf(gi) * tanhf(gu) + fa * ca + fb * cb;
        g_c[(size_t)par * Hh + m] = ct2;
        h[(size_t)par * Hh + m]   = sigf(go) * tanhf(ct2);
    }
}

// ---------------------------------------------------------------------------
extern "C" void kernel_launch(void* const* d_in, const int* in_sizes, int n_in,
                              void* d_out, int out_size) {
    const float* x      = (const float*)d_in[0];
    const float* labels = (const float*)d_in[1];   // [15,6000,1]
    const float* W_iou  = (const float*)d_in[2];
    const float* W_f    = (const float*)d_in[3];
    const float* b_iou  = (const float*)d_in[4];
    const float* b_f    = (const float*)d_in[5];
    const float* U_iou  = (const float*)d_in[6];
    const float* U_f    = (const float*)d_in[7];
    const int*   edges  = (const int*)d_in[8];     // [15,2,6000]
    const int*   order0 = (const int*)d_in[9];
    float* h = (float*)d_out;                      // h lives directly in d_out

    cudaFuncSetAttribute(k_pre,   cudaFuncAttributeMaxDynamicSharedMemorySize, PRE_SMEMB);
    cudaFuncSetAttribute(k_round, cudaFuncAttributeMaxDynamicSharedMemorySize, RND_SMEMB);

    k_transU<<<512, 256>>>(U_iou, U_f);
    k_transW<<<256, 256>>>(W_iou, W_f);
    k_pre<<<1500, 256, PRE_SMEMB>>>(x);
    k_round0<<<(NPRc * Hh + 255) / 256, 256>>>(h, order0, b_iou);
    for (int ri = 0; ri < 15; ri++)
        k_round<<<148, 512, RND_SMEMB>>>(ri, h, b_iou, b_f, edges, labels);
}